// round 12
// baseline (speedup 1.0000x reference)
#include <cuda_runtime.h>
#include <cuda_bf16.h>

// Welford running mean/variance over batch dim of x: (B, C, H, W), B=256, CHW=262144.
// One scalar thread per spatial position (262,144 threads).
//
// R12 = R4 (dual half-batch Welford streams, exact Chan merge; best bench @92.2)
//       + R8 prefetch-1 pipeline, with NO launch_bounds. R10 showed the pipeline
//       gives the best per-warp throughput measured (DRAM/occ=1.12) but its reg cap
//       cost 20 points of occupancy. Letting ptxas target its default 32-reg /
//       full-occupancy point keeps R4's warp pool; worst case ptxas serializes the
//       prefetch and this degrades to exactly R4.
//
// Output layout (float32, concatenated):
//   [0, B*CHW) : x passthrough | [+0,+CHW): m | [+CHW,+2CHW): s
//   [+2CHW,+3CHW): neuron_nonzero | [last]: n_samples + B

__global__ void welford_dual_pipe_nb(
    const float* __restrict__ x,
    const float* __restrict__ m_in,
    const float* __restrict__ s_in,
    const int*   __restrict__ nn_in,
    const int*   __restrict__ n_in,
    float*       __restrict__ out,
    int B, int CHW)
{
    int p = blockIdx.x * blockDim.x + threadIdx.x;
    if (p >= CHW) return;

    const int H  = B >> 1;                 // 128
    const int n0 = n_in[0];
    const size_t step = (size_t)CHW;

    // Stream A continues the input state over b in [0, H);
    // Stream B runs standalone from zero over b in [H, B).
    float mA = m_in[p], sA = s_in[p];
    float mB = 0.0f,    sB = 0.0f;
    int   nnA = nn_in[p], nnB = 0;

    const float* xA = x + p;
    const float* xB = x + p + (size_t)H * step;
    float*       oA = out + p;
    float*       oB = out + p + (size_t)H * step;

    // Prologue: prefetch first sample of each stream.
    float vA = xA[0];
    float vB = xB[0];

    float nfA = (float)n0;
    float nfB = 0.0f;

    for (int b = 0; b < H - 1; ++b) {
        // Phase 1: issue next-iteration loads (independent of all pending work).
        size_t noff = (size_t)(b + 1) * step;
        float wA = xA[noff];
        float wB = xB[noff];

        // Phase 2: passthrough stores + Welford on current samples
        // (their data arrived during the previous iteration).
        size_t coff = (size_t)b * step;
        oA[coff] = vA;
        oB[coff] = vB;

        nnA += (vA != 0.0f);
        nnB += (vB != 0.0f);
        float invA = __fdividef(1.0f, nfA + 1.0f);
        float invB = __fdividef(1.0f, nfB + 1.0f);
        float om;
        om = mA; mA += (vA - mA) * invA; sA += (vA - mA) * (vA - om);
        om = mB; mB += (vB - mB) * invB; sB += (vB - mB) * (vB - om);
        nfA += 1.0f;
        nfB += 1.0f;

        vA = wA; vB = wB;
    }

    // Epilogue: last sample of each stream.
    {
        size_t coff = (size_t)(H - 1) * step;
        oA[coff] = vA;
        oB[coff] = vB;

        nnA += (vA != 0.0f);
        nnB += (vB != 0.0f);
        float invA = __fdividef(1.0f, nfA + 1.0f);
        float invB = __fdividef(1.0f, nfB + 1.0f);
        float om;
        om = mA; mA += (vA - mA) * invA; sA += (vA - mA) * (vA - om);
        om = mB; mB += (vB - mB) * invB; sB += (vB - mB) * (vB - om);
    }

    // Exact Chan merge: A carries n0+H samples, B carries H samples.
    float nAf = (float)(n0 + H);
    float nBf = (float)H;
    float nTf = nAf + nBf;
    float invT = __fdividef(1.0f, nTf);
    float d  = mB - mA;
    float m  = mA + d * (nBf * invT);
    float s  = sA + sB + d * d * (nAf * nBf * invT);
    int   nn = nnA + nnB;

    size_t base = (size_t)B * step;
    out[base + p]            = m;
    out[base + step + p]     = s;
    out[base + 2 * step + p] = (float)nn;
    if (p == 0) {
        out[base + 3 * step] = (float)(n0 + B);
    }
}

extern "C" void kernel_launch(void* const* d_in, const int* in_sizes, int n_in,
                              void* d_out, int out_size)
{
    const float* x  = (const float*)d_in[0];
    const float* m  = (const float*)d_in[1];
    const float* s  = (const float*)d_in[2];
    const int*   nn = (const int*)d_in[3];
    const int*   n  = (const int*)d_in[4];
    float* out = (float*)d_out;

    const int CHW = in_sizes[1];          // 262144
    const int B   = in_sizes[0] / CHW;    // 256

    const int threads = 256;
    const int blocks = (CHW + threads - 1) / threads;  // 1024
    welford_dual_pipe_nb<<<blocks, threads>>>(x, m, s, nn, n, out, B, CHW);
}

// round 13
// speedup vs baseline: 1.1022x; 1.1022x over previous
#include <cuda_runtime.h>
#include <cuda_bf16.h>

// Welford running mean/variance over batch dim of x: (B, C, H, W), B=256, CHW=262144.
// One scalar thread per spatial position (262,144 threads).
//
// R13 = R4 (dual half-batch Welford streams + exact Chan merge; best bench @92.2,
//       regs=32, occ 81%) with the per-iteration scalar fat removed:
//       the reciprocals 1/(n0+b+1) and 1/(b+1) are thread-invariant, so they are
//       precomputed once per block into a 1 KB shared-memory table (broadcast LDS,
//       conflict-free) replacing 2 MUFU + 2 FADD per loop iteration. Same memory
//       pattern, same register budget, same numerics.
//
// Output layout (float32, concatenated):
//   [0, B*CHW) : x passthrough | [+0,+CHW): m | [+CHW,+2CHW): s
//   [+2CHW,+3CHW): neuron_nonzero | [last]: n_samples + B

__global__ void __launch_bounds__(256) welford_dual_tab(
    const float* __restrict__ x,
    const float* __restrict__ m_in,
    const float* __restrict__ s_in,
    const int*   __restrict__ nn_in,
    const int*   __restrict__ n_in,
    float*       __restrict__ out,
    int B, int CHW)
{
    __shared__ float invA_tab[128];
    __shared__ float invB_tab[128];

    const int H  = B >> 1;                 // 128
    const int n0 = n_in[0];

    // Build reciprocal tables once per block (identical math to R4's loop).
    {
        int t = threadIdx.x;
        if (t < H) {
            invA_tab[t] = __fdividef(1.0f, (float)(n0 + t + 1));
            invB_tab[t] = __fdividef(1.0f, (float)(t + 1));
        }
    }
    __syncthreads();

    int p = blockIdx.x * blockDim.x + threadIdx.x;
    if (p >= CHW) return;

    const size_t step = (size_t)CHW;

    // Stream A continues the input state over b in [0, H);
    // Stream B runs standalone from zero over b in [H, B).
    float mA = m_in[p], sA = s_in[p];
    float mB = 0.0f,    sB = 0.0f;
    int   nnA = nn_in[p], nnB = 0;

    const float* xA = x + p;
    const float* xB = x + p + (size_t)H * step;
    float*       oA = out + p;
    float*       oB = out + p + (size_t)H * step;

    #pragma unroll 4
    for (int b = 0; b < H; ++b) {
        float va = xA[(size_t)b * step];
        float vb = xB[(size_t)b * step];
        oA[(size_t)b * step] = va;          // passthrough
        oB[(size_t)b * step] = vb;

        nnA += (va != 0.0f);
        nnB += (vb != 0.0f);

        float invA = invA_tab[b];           // broadcast LDS (N=1)
        float invB = invB_tab[b];

        float om;
        om = mA; mA += (va - mA) * invA; sA += (va - mA) * (va - om);
        om = mB; mB += (vb - mB) * invB; sB += (vb - mB) * (vb - om);
    }

    // Exact Chan merge: A carries n0+H samples, B carries H samples.
    float nAf = (float)(n0 + H);
    float nBf = (float)H;
    float nTf = nAf + nBf;
    float invT = __fdividef(1.0f, nTf);
    float d  = mB - mA;
    float m  = mA + d * (nBf * invT);
    float s  = sA + sB + d * d * (nAf * nBf * invT);
    int   nn = nnA + nnB;

    size_t base = (size_t)B * step;
    out[base + p]            = m;
    out[base + step + p]     = s;
    out[base + 2 * step + p] = (float)nn;
    if (p == 0) {
        out[base + 3 * step] = (float)(n0 + B);
    }
}

extern "C" void kernel_launch(void* const* d_in, const int* in_sizes, int n_in,
                              void* d_out, int out_size)
{
    const float* x  = (const float*)d_in[0];
    const float* m  = (const float*)d_in[1];
    const float* s  = (const float*)d_in[2];
    const int*   nn = (const int*)d_in[3];
    const int*   n  = (const int*)d_in[4];
    float* out = (float*)d_out;

    const int CHW = in_sizes[1];          // 262144
    const int B   = in_sizes[0] / CHW;    // 256

    const int threads = 256;
    const int blocks = (CHW + threads - 1) / threads;  // 1024
    welford_dual_tab<<<blocks, threads>>>(x, m, s, nn, n, out, B, CHW);
}